// round 2
// baseline (speedup 1.0000x reference)
#include <cuda_runtime.h>
#include <cstdint>

// Problem constants
static constexpr int   B_   = 16;
static constexpr int   N_   = 1024;
static constexpr float TAU_ = 0.5f;
static constexpr float EPS_ = 1e-10f;
static constexpr int   NSQ  = N_ * N_;        // 1048576
static constexpr int   NB   = B_ * N_;        // 16384 nodes total

// ---------------------------------------------------------------------------
// Scratch (device globals; allocation is forbidden)
// ---------------------------------------------------------------------------
__device__ float g_adj  [B_ * NSQ];          // 64 MB  adj[b,i,j]
__device__ float g_adjT [B_ * NSQ];          // 64 MB  adj[b,j,i]
__device__ float g_rowsum[NB];
__device__ float g_colsum[NB];
__device__ float g_xcat [NB * 128];          // [xin | h]
__device__ float g_p0   [NB * 128];          // adj  @ xcat
__device__ float g_p1   [NB * 128];          // adjT @ xcat
__device__ float g_rh   [NB * 64];           // r * h
__device__ float g_u    [NB * 64];           // update gate
__device__ float g_q0   [NB * 64];           // adj  @ rh
__device__ float g_q1   [NB * 64];           // adjT @ rh
__device__ float g_xeff [NB * 384];          // effective GEMM input (pass1 & pass2)
__device__ float g_val  [NB * 128];          // pre-activation gates
__device__ float g_cpre [NB * 64];           // pre-activation candidate
__device__ float g_w1t  [384 * 128];         // effective gate weights, (k, o)
__device__ float g_w2t  [384 * 64];          // effective candidate weights, (k, o)
__device__ float g_b1   [128];
__device__ float g_b2   [64];

// ---------------------------------------------------------------------------
// K0: fold weights. The reference's diffusion loop appends `prev` twice
// (A^2 x is computed but never used), so steps 1 and 2 both multiply Ax:
// their weight columns can be pre-summed. Also combine the two biases and
// zero the row/col-sum accumulators.
// ---------------------------------------------------------------------------
__global__ void k0_prep(const float* __restrict__ W0, const float* __restrict__ b0,
                        const float* __restrict__ W1, const float* __restrict__ b1,
                        const float* __restrict__ Wc0, const float* __restrict__ bc0,
                        const float* __restrict__ Wc1, const float* __restrict__ bc1)
{
    int idx    = blockIdx.x * blockDim.x + threadIdx.x;
    int stride = gridDim.x * blockDim.x;

    for (int i = idx; i < 384 * 128; i += stride) {
        int k = i / 128, o = i % 128;
        float v;
        if (k < 128)       { int c = k;        v = W0[o*384 + 3*c]     + W1[o*384 + 3*c];     }
        else if (k < 256)  { int c = k - 128;  v = W0[o*384 + 3*c + 1] + W0[o*384 + 3*c + 2]; }
        else               { int c = k - 256;  v = W1[o*384 + 3*c + 1] + W1[o*384 + 3*c + 2]; }
        g_w1t[i] = v;
    }
    for (int i = idx; i < 384 * 64; i += stride) {
        int k = i / 64, o = i % 64;
        float v;
        if (k < 128)       { int c = k;        v = Wc0[o*384 + 3*c]     + Wc1[o*384 + 3*c];     }
        else if (k < 256)  { int c = k - 128;  v = Wc0[o*384 + 3*c + 1] + Wc0[o*384 + 3*c + 2]; }
        else               { int c = k - 256;  v = Wc1[o*384 + 3*c + 1] + Wc1[o*384 + 3*c + 2]; }
        g_w2t[i] = v;
    }
    for (int i = idx; i < 128; i += stride) g_b1[i] = b0[i] + b1[i];
    for (int i = idx; i < 64;  i += stride) g_b2[i] = bc0[i] + bc1[i];
    for (int i = idx; i < NB;  i += stride) { g_rowsum[i] = 0.f; g_colsum[i] = 0.f; }
}

// ---------------------------------------------------------------------------
// K1: Gumbel-softmax adjacency + transpose + row/col sums (fused).
// z_i = l_i - log(g_i), g_i = EPS - log(u_i + EPS)
// adj = softmax(z/tau)[0] = 1 / (1 + exp((z1 - z0)/tau))
// 32x32 tiles, block (32,8); each thread covers 4 rows.
// ---------------------------------------------------------------------------
__global__ void k1_gumbel(const float* __restrict__ logits,
                          const float* __restrict__ unoise)
{
    __shared__ float s[32][33];
    __shared__ float scol[8][32];

    const int b  = blockIdx.z;
    const int i0 = blockIdx.y * 32;
    const int j0 = blockIdx.x * 32;
    const int tx = threadIdx.x;        // 0..31 (lane)
    const int ty = threadIdx.y;        // 0..7  (warp id)

    const float2* lg = reinterpret_cast<const float2*>(logits) + (size_t)b * NSQ;
    const float2* un = reinterpret_cast<const float2*>(unoise) + (size_t)b * NSQ;

    float vals[4];
#pragma unroll
    for (int sI = 0; sI < 4; ++sI) {
        int row  = ty + 8 * sI;
        size_t e = (size_t)(i0 + row) * N_ + (j0 + tx);
        float2 l = lg[e];
        float2 u = un[e];
        float g0 = EPS_ - __logf(u.x + EPS_);
        float g1 = EPS_ - __logf(u.y + EPS_);
        // (z1 - z0)/tau = ((l1-l0) + log(g0) - log(g1)) / tau
        float t  = ((l.y - l.x) + (__logf(g0) - __logf(g1))) * (1.0f / TAU_);
        float a  = 1.0f / (1.0f + __expf(t));
        vals[sI]   = a;
        s[row][tx] = a;
        g_adj[(size_t)b * NSQ + e] = a;
    }

    // row sums of adj (sum over j): each warp owns 4 rows, reduce over lanes
#pragma unroll
    for (int sI = 0; sI < 4; ++sI) {
        float v = vals[sI];
#pragma unroll
        for (int o = 16; o > 0; o >>= 1) v += __shfl_down_sync(0xffffffffu, v, o);
        if (tx == 0) atomicAdd(&g_rowsum[b * N_ + i0 + ty + 8 * sI], v);
    }

    // column sums (sum over i): per-lane partial over the 4 covered rows
    scol[ty][tx] = vals[0] + vals[1] + vals[2] + vals[3];
    __syncthreads();

    if (ty == 0) {
        float t2 = 0.f;
#pragma unroll
        for (int w = 0; w < 8; ++w) t2 += scol[w][tx];
        atomicAdd(&g_colsum[b * N_ + j0 + tx], t2);
    }

    // transposed write (coalesced via shared tile)
#pragma unroll
    for (int sI = 0; sI < 4; ++sI) {
        int jj = ty + 8 * sI;
        g_adjT[(size_t)b * NSQ + (size_t)(j0 + jj) * N_ + i0 + tx] = s[tx][jj];
    }
}

// ---------------------------------------------------------------------------
// K2: xcat = [xin | h]  (B,N,128)
// ---------------------------------------------------------------------------
__global__ void k2_xcat(const float* __restrict__ inp, const float* __restrict__ hx)
{
    size_t idx = (size_t)blockIdx.x * blockDim.x + threadIdx.x;
    if (idx >= (size_t)NB * 128) return;
    size_t node = idx >> 7;
    int c = (int)(idx & 127);
    g_xcat[idx] = (c < 64) ? inp[node * 64 + c] : hx[node * 64 + (c - 64)];
}

// ---------------------------------------------------------------------------
// Tiled fp32 GEMM core: Y tile = A(M x Kd, row-major) @ X(Kd x C)
// Pointers already offset for the batch. blockIdx.y -> M tile, blockIdx.x -> C tile.
// ---------------------------------------------------------------------------
template<int BM, int BN, int BK, int TM, int TN>
__device__ __forceinline__ void gemm_core(const float* __restrict__ A,
                                          const float* __restrict__ X,
                                          float* __restrict__ Y,
                                          int Kd, int C)
{
    constexpr int THREADS = (BM / TM) * (BN / TN);
    __shared__ float As[BK][BM];
    __shared__ float Bs[BK][BN];

    const int tid = threadIdx.x;
    const int tx  = tid % (BN / TN);
    const int ty  = tid / (BN / TN);
    const int rowBase = blockIdx.y * BM;
    const int colBase = blockIdx.x * BN;

    float acc[TM][TN];
#pragma unroll
    for (int i = 0; i < TM; ++i)
#pragma unroll
        for (int j = 0; j < TN; ++j) acc[i][j] = 0.f;

    for (int k0 = 0; k0 < Kd; k0 += BK) {
        // A tile (BM x BK), stored transposed in shared
#pragma unroll
        for (int i = tid; i < BM * BK / 4; i += THREADS) {
            int m  = i / (BK / 4);
            int kq = i % (BK / 4);
            float4 v = *reinterpret_cast<const float4*>(
                A + (size_t)(rowBase + m) * Kd + k0 + kq * 4);
            As[kq * 4 + 0][m] = v.x;
            As[kq * 4 + 1][m] = v.y;
            As[kq * 4 + 2][m] = v.z;
            As[kq * 4 + 3][m] = v.w;
        }
        // X tile (BK x BN)
#pragma unroll
        for (int i = tid; i < BK * BN / 4; i += THREADS) {
            int kr = i / (BN / 4);
            int cq = i % (BN / 4);
            *reinterpret_cast<float4*>(&Bs[kr][cq * 4]) =
                *reinterpret_cast<const float4*>(X + (size_t)(k0 + kr) * C + colBase + cq * 4);
        }
        __syncthreads();

#pragma unroll
        for (int k = 0; k < BK; ++k) {
            float a[TM], bf[TN];
#pragma unroll
            for (int i = 0; i < TM; ++i) a[i]  = As[k][ty * TM + i];
#pragma unroll
            for (int j = 0; j < TN; ++j) bf[j] = Bs[k][tx * TN + j];
#pragma unroll
            for (int i = 0; i < TM; ++i)
#pragma unroll
                for (int j = 0; j < TN; ++j)
                    acc[i][j] = fmaf(a[i], bf[j], acc[i][j]);
        }
        __syncthreads();
    }

#pragma unroll
    for (int i = 0; i < TM; ++i) {
#pragma unroll
        for (int j = 0; j < TN; j += 4) {
            float4 v = make_float4(acc[i][j], acc[i][j+1], acc[i][j+2], acc[i][j+3]);
            *reinterpret_cast<float4*>(
                Y + (size_t)(rowBase + ty * TM + i) * C + colBase + tx * TN + j) = v;
        }
    }
}

// K3: p0 = adj@xcat, p1 = adjT@xcat. z in [0,32): b = z%16, sel = z/16.
__global__ __launch_bounds__(256)
void k3_pair128()
{
    int z   = blockIdx.z;
    int b   = z & 15;
    int sel = z >> 4;
    const float* A = sel ? g_adjT : g_adj;
    float*       Y = sel ? g_p1   : g_p0;
    gemm_core<128, 128, 16, 8, 8>(A + (size_t)b * NSQ,
                                  g_xcat + (size_t)b * N_ * 128,
                                  Y      + (size_t)b * N_ * 128, N_, 128);
}

// K6: q0 = adj@rh, q1 = adjT@rh  (C = 64)
__global__ __launch_bounds__(128)
void k6_pair64()
{
    int z   = blockIdx.z;
    int b   = z & 15;
    int sel = z >> 4;
    const float* A = sel ? g_adjT : g_adj;
    float*       Y = sel ? g_q1   : g_q0;
    gemm_core<128, 64, 16, 8, 8>(A + (size_t)b * NSQ,
                                 g_rh + (size_t)b * N_ * 64,
                                 Y    + (size_t)b * N_ * 64, N_, 64);
}

// K4b: gate projection  val = xeff @ w1t   (M = 16384, Kd = 384, C = 128)
__global__ __launch_bounds__(256)
void k4b_gemm_gate()
{
    gemm_core<128, 128, 16, 8, 8>(g_xeff, g_w1t, g_val, 384, 128);
}

// K8: candidate projection  cpre = xeff @ w2t  (M = 16384, Kd = 384, C = 64)
__global__ __launch_bounds__(128)
void k8_gemm_cand()
{
    gemm_core<128, 64, 16, 8, 8>(g_xeff, g_w2t, g_cpre, 384, 64);
}

// ---------------------------------------------------------------------------
// K4: effective gate input:
// xeff = [ xcat | (p0+xcat)/(colsum+1) | (p1+xcat)/(rowsum+1) ]
// ---------------------------------------------------------------------------
__global__ void k4_xeff1()
{
    size_t idx = (size_t)blockIdx.x * blockDim.x + threadIdx.x;
    if (idx >= (size_t)NB * 384) return;
    size_t node = idx / 384;
    int k = (int)(idx % 384);
    float v;
    if (k < 128) {
        v = g_xcat[node * 128 + k];
    } else if (k < 256) {
        int c = k - 128;
        v = (g_p0[node * 128 + c] + g_xcat[node * 128 + c]) / (g_colsum[node] + 1.f);
    } else {
        int c = k - 256;
        v = (g_p1[node * 128 + c] + g_xcat[node * 128 + c]) / (g_rowsum[node] + 1.f);
    }
    g_xeff[idx] = v;
}

// ---------------------------------------------------------------------------
// K5: gates r,u = sigmoid(val + bias); rh = r*h; keep u
// ---------------------------------------------------------------------------
__global__ void k5_act(const float* __restrict__ hx)
{
    size_t idx = (size_t)blockIdx.x * blockDim.x + threadIdx.x;
    if (idx >= (size_t)NB * 64) return;
    size_t node = idx / 64;
    int o = (int)(idx % 64);
    float r = 1.f / (1.f + __expf(-(g_val[node * 128 + o]      + g_b1[o])));
    float u = 1.f / (1.f + __expf(-(g_val[node * 128 + 64 + o] + g_b1[64 + o])));
    g_u[idx]  = u;
    g_rh[idx] = r * hx[idx];
}

// ---------------------------------------------------------------------------
// K7: effective candidate input (reuses pass-1 p0/p1 for xin channels;
// only r*h channels needed the new SpMM q0/q1)
// ---------------------------------------------------------------------------
__global__ void k7_xeff2()
{
    size_t idx = (size_t)blockIdx.x * blockDim.x + threadIdx.x;
    if (idx >= (size_t)NB * 384) return;
    size_t node = idx / 384;
    int k = (int)(idx % 384);
    float invc = 1.f / (g_colsum[node] + 1.f);
    float invr = 1.f / (g_rowsum[node] + 1.f);
    float v;
    if      (k < 64)  v = g_xcat[node * 128 + k];                                         // xin
    else if (k < 128) v = g_rh[node * 64 + (k - 64)];                                     // r*h
    else if (k < 192) { int c = k - 128; v = (g_p0[node*128 + c] + g_xcat[node*128 + c]) * invc; }
    else if (k < 256) { int c = k - 192; v = (g_q0[node*64  + c] + g_rh [node*64  + c]) * invc; }
    else if (k < 320) { int c = k - 256; v = (g_p1[node*128 + c] + g_xcat[node*128 + c]) * invr; }
    else              { int c = k - 320; v = (g_q1[node*64  + c] + g_rh [node*64  + c]) * invr; }
    g_xeff[idx] = v;
}

// ---------------------------------------------------------------------------
// K9: c = tanh(cpre + bias); out = u*h + (1-u)*c
// ---------------------------------------------------------------------------
__global__ void k9_final(const float* __restrict__ hx, float* __restrict__ out)
{
    size_t idx = (size_t)blockIdx.x * blockDim.x + threadIdx.x;
    if (idx >= (size_t)NB * 64) return;
    int o = (int)(idx % 64);
    float c = tanhf(g_cpre[idx] + g_b2[o]);
    float u = g_u[idx];
    out[idx] = u * hx[idx] + (1.f - u) * c;
}

// ---------------------------------------------------------------------------
// Launch: kernel launches only (graph-capture safe; no runtime API calls)
// ---------------------------------------------------------------------------
extern "C" void kernel_launch(void* const* d_in, const int* in_sizes, int n_in,
                              void* d_out, int out_size)
{
    const float* logits = (const float*)d_in[0];
    const float* unoise = (const float*)d_in[1];
    const float* inputs = (const float*)d_in[2];
    const float* hx     = (const float*)d_in[3];
    const float* W0     = (const float*)d_in[4];
    const float* b0     = (const float*)d_in[5];
    const float* W1     = (const float*)d_in[6];
    const float* b1     = (const float*)d_in[7];
    const float* Wc0    = (const float*)d_in[8];
    const float* bc0    = (const float*)d_in[9];
    const float* Wc1    = (const float*)d_in[10];
    const float* bc1    = (const float*)d_in[11];
    float* out          = (float*)d_out;

    k0_prep<<<128, 256>>>(W0, b0, W1, b1, Wc0, bc0, Wc1, bc1);

    k1_gumbel<<<dim3(N_/32, N_/32, B_), dim3(32, 8)>>>(logits, unoise);

    k2_xcat<<<(NB * 128 + 255) / 256, 256>>>(inputs, hx);

    k3_pair128<<<dim3(1, N_/128, 2 * B_), 256>>>();

    k4_xeff1<<<(NB * 384 + 255) / 256, 256>>>();

    k4b_gemm_gate<<<dim3(1, NB/128, 1), 256>>>();

    k5_act<<<(NB * 64 + 255) / 256, 256>>>(hx);

    k6_pair64<<<dim3(1, N_/128, 2 * B_), 128>>>();

    k7_xeff2<<<(NB * 384 + 255) / 256, 256>>>();

    k8_gemm_cand<<<dim3(1, NB/128, 1), 128>>>();

    k9_final<<<(NB * 64 + 255) / 256, 256>>>(hx, out);
}

// round 3
// speedup vs baseline: 1.6962x; 1.6962x over previous
#include <cuda_runtime.h>
#include <cstdint>

// Problem constants
static constexpr int   B_   = 16;
static constexpr int   N_   = 1024;
static constexpr float TAU_ = 0.5f;
static constexpr float EPS_ = 1e-10f;
static constexpr int   NSQ  = N_ * N_;        // 1048576
static constexpr int   NB   = B_ * N_;        // 16384 nodes total

// ---------------------------------------------------------------------------
// Scratch (device globals; allocation is forbidden)
// ---------------------------------------------------------------------------
__device__ float g_adj  [B_ * NSQ];          // 64 MB  adj[b,i,j]
__device__ float g_rowsum[NB];
__device__ float g_colsum[NB];
__device__ float g_xcat [NB * 128];          // [xin | h]
__device__ float g_p0   [NB * 128];          // adj  @ xcat
__device__ float g_p1   [NB * 128];          // adjT @ xcat
__device__ float g_rh   [NB * 64];           // r * h
__device__ float g_u    [NB * 64];           // update gate
__device__ float g_q0   [NB * 64];           // adj  @ rh
__device__ float g_q1   [NB * 64];           // adjT @ rh
__device__ float g_xeff [NB * 384];          // effective GEMM input (pass1 & pass2)
__device__ float g_val  [NB * 128];          // pre-activation gates
__device__ float g_cpre [NB * 64];           // pre-activation candidate
__device__ float g_w1t  [384 * 128];         // effective gate weights, (k, o)
__device__ float g_w2t  [384 * 64];          // effective candidate weights, (k, o)
__device__ float g_b1   [128];
__device__ float g_b2   [64];

// ---------------------------------------------------------------------------
// TF32 helpers
// ---------------------------------------------------------------------------
__device__ __forceinline__ float to_tf32(float x)
{
    uint32_t u;
    asm("cvt.rna.tf32.f32 %0, %1;" : "=r"(u) : "f"(x));
    return __uint_as_float(u);
}

__device__ __forceinline__ void mma_m16n8k8(float c[4],
                                            uint32_t a0, uint32_t a1, uint32_t a2, uint32_t a3,
                                            uint32_t b0, uint32_t b1)
{
    asm volatile("mma.sync.aligned.m16n8k8.row.col.f32.tf32.tf32.f32 "
                 "{%0,%1,%2,%3}, {%4,%5,%6,%7}, {%8,%9}, {%0,%1,%2,%3};\n"
                 : "+f"(c[0]), "+f"(c[1]), "+f"(c[2]), "+f"(c[3])
                 : "r"(a0), "r"(a1), "r"(a2), "r"(a3), "r"(b0), "r"(b1));
}

// ---------------------------------------------------------------------------
// K0: fold weights (the reference's diffusion appends `prev` twice, so steps
// 1 and 2 both multiply Ax -> pre-sum their weight columns), combine biases,
// zero the sum accumulators.
// ---------------------------------------------------------------------------
__global__ void k0_prep(const float* __restrict__ W0, const float* __restrict__ b0,
                        const float* __restrict__ W1, const float* __restrict__ b1,
                        const float* __restrict__ Wc0, const float* __restrict__ bc0,
                        const float* __restrict__ Wc1, const float* __restrict__ bc1)
{
    int idx    = blockIdx.x * blockDim.x + threadIdx.x;
    int stride = gridDim.x * blockDim.x;

    for (int i = idx; i < 384 * 128; i += stride) {
        int k = i / 128, o = i % 128;
        float v;
        if (k < 128)       { int c = k;        v = W0[o*384 + 3*c]     + W1[o*384 + 3*c];     }
        else if (k < 256)  { int c = k - 128;  v = W0[o*384 + 3*c + 1] + W0[o*384 + 3*c + 2]; }
        else               { int c = k - 256;  v = W1[o*384 + 3*c + 1] + W1[o*384 + 3*c + 2]; }
        g_w1t[i] = v;
    }
    for (int i = idx; i < 384 * 64; i += stride) {
        int k = i / 64, o = i % 64;
        float v;
        if (k < 128)       { int c = k;        v = Wc0[o*384 + 3*c]     + Wc1[o*384 + 3*c];     }
        else if (k < 256)  { int c = k - 128;  v = Wc0[o*384 + 3*c + 1] + Wc0[o*384 + 3*c + 2]; }
        else               { int c = k - 256;  v = Wc1[o*384 + 3*c + 1] + Wc1[o*384 + 3*c + 2]; }
        g_w2t[i] = v;
    }
    for (int i = idx; i < 128; i += stride) g_b1[i] = b0[i] + b1[i];
    for (int i = idx; i < 64;  i += stride) g_b2[i] = bc0[i] + bc1[i];
    for (int i = idx; i < NB;  i += stride) { g_rowsum[i] = 0.f; g_colsum[i] = 0.f; }
}

// ---------------------------------------------------------------------------
// K1: Gumbel-softmax adjacency + row/col sums (fused). No transposed copy:
// the sel=1 GEMMs read adj K-major directly.
// z_i = l_i - log(g_i), g_i = EPS - log(u_i + EPS)
// adj = softmax(z/tau)[0] = 1 / (1 + exp((z1 - z0)/tau))
// ---------------------------------------------------------------------------
__global__ void k1_gumbel(const float* __restrict__ logits,
                          const float* __restrict__ unoise)
{
    __shared__ float scol[8][32];

    const int b  = blockIdx.z;
    const int i0 = blockIdx.y * 32;
    const int j0 = blockIdx.x * 32;
    const int tx = threadIdx.x;        // 0..31 (lane)
    const int ty = threadIdx.y;        // 0..7  (warp id)

    const float2* lg = reinterpret_cast<const float2*>(logits) + (size_t)b * NSQ;
    const float2* un = reinterpret_cast<const float2*>(unoise) + (size_t)b * NSQ;

    float vals[4];
#pragma unroll
    for (int sI = 0; sI < 4; ++sI) {
        int row  = ty + 8 * sI;
        size_t e = (size_t)(i0 + row) * N_ + (j0 + tx);
        float2 l = lg[e];
        float2 u = un[e];
        float g0 = EPS_ - __logf(u.x + EPS_);
        float g1 = EPS_ - __logf(u.y + EPS_);
        float t  = ((l.y - l.x) + (__logf(g0) - __logf(g1))) * (1.0f / TAU_);
        float a  = 1.0f / (1.0f + __expf(t));
        vals[sI] = a;
        g_adj[(size_t)b * NSQ + e] = a;
    }

    // row sums (sum over j)
#pragma unroll
    for (int sI = 0; sI < 4; ++sI) {
        float v = vals[sI];
#pragma unroll
        for (int o = 16; o > 0; o >>= 1) v += __shfl_down_sync(0xffffffffu, v, o);
        if (tx == 0) atomicAdd(&g_rowsum[b * N_ + i0 + ty + 8 * sI], v);
    }

    // column sums (sum over i)
    scol[ty][tx] = vals[0] + vals[1] + vals[2] + vals[3];
    __syncthreads();
    if (ty == 0) {
        float t2 = 0.f;
#pragma unroll
        for (int w = 0; w < 8; ++w) t2 += scol[w][tx];
        atomicAdd(&g_colsum[b * N_ + j0 + tx], t2);
    }
}

// ---------------------------------------------------------------------------
// K2: xcat = [xin | h]  (B,N,128)
// ---------------------------------------------------------------------------
__global__ void k2_xcat(const float* __restrict__ inp, const float* __restrict__ hx)
{
    size_t idx = (size_t)blockIdx.x * blockDim.x + threadIdx.x;
    if (idx >= (size_t)NB * 128) return;
    size_t node = idx >> 7;
    int c = (int)(idx & 127);
    g_xcat[idx] = (c < 64) ? inp[node * 64 + c] : hx[node * 64 + (c - 64)];
}

// ---------------------------------------------------------------------------
// TF32 tensor-core GEMM core: Y = op(A) @ X
//   a_kmajor = false : A is row-major M x Kd (element (m,k) at A[m*ldA + k])
//   a_kmajor = true  : A stored K-major      (element (m,k) at A[k*ldA + m])
//                      i.e. computes A^T @ X for a row-major A — used for adjT.
// BM x BN block tile, BK k-tile, WARPS_M x WARPS_N warps, m16n8k8 atoms.
// Shared tiles padded (+8) so fragment loads hit 32 distinct banks.
// ---------------------------------------------------------------------------
template<int BM, int BN, int BK, int WARPS_M, int WARPS_N>
__device__ __forceinline__ void mma_core(const float* __restrict__ A,
                                         const float* __restrict__ X,
                                         float* __restrict__ Y,
                                         int Kd, int C, int ldA, bool a_kmajor,
                                         float (*As)[BM + 8], float (*Bs)[BN + 8])
{
    constexpr int THREADS = WARPS_M * WARPS_N * 32;
    constexpr int WM = BM / WARPS_M;
    constexpr int WN = BN / WARPS_N;
    constexpr int MI = WM / 16;
    constexpr int NI = WN / 8;

    const int tid  = threadIdx.x;
    const int lane = tid & 31;
    const int w    = tid >> 5;
    const int wm   = w / WARPS_N;
    const int wn   = w % WARPS_N;
    const int grp  = lane >> 2;     // 0..7
    const int qid  = lane & 3;      // 0..3
    const int rowBase = blockIdx.y * BM;
    const int colBase = blockIdx.x * BN;

    float acc[MI][NI][4];
#pragma unroll
    for (int mi = 0; mi < MI; ++mi)
#pragma unroll
        for (int ni = 0; ni < NI; ++ni)
#pragma unroll
            for (int r = 0; r < 4; ++r) acc[mi][ni][r] = 0.f;

    for (int k0 = 0; k0 < Kd; k0 += BK) {
        if (a_kmajor) {
#pragma unroll
            for (int i = tid; i < BK * (BM / 4); i += THREADS) {
                int kr = i / (BM / 4);
                int mq = i % (BM / 4);
                float4 v = *reinterpret_cast<const float4*>(
                    A + (size_t)(k0 + kr) * ldA + rowBase + mq * 4);
                As[kr][mq * 4 + 0] = to_tf32(v.x);
                As[kr][mq * 4 + 1] = to_tf32(v.y);
                As[kr][mq * 4 + 2] = to_tf32(v.z);
                As[kr][mq * 4 + 3] = to_tf32(v.w);
            }
        } else {
#pragma unroll
            for (int i = tid; i < BM * (BK / 4); i += THREADS) {
                int m  = i / (BK / 4);
                int kq = i % (BK / 4);
                float4 v = *reinterpret_cast<const float4*>(
                    A + (size_t)(rowBase + m) * ldA + k0 + kq * 4);
                As[kq * 4 + 0][m] = to_tf32(v.x);
                As[kq * 4 + 1][m] = to_tf32(v.y);
                As[kq * 4 + 2][m] = to_tf32(v.z);
                As[kq * 4 + 3][m] = to_tf32(v.w);
            }
        }
#pragma unroll
        for (int i = tid; i < BK * (BN / 4); i += THREADS) {
            int kr = i / (BN / 4);
            int cq = i % (BN / 4);
            float4 v = *reinterpret_cast<const float4*>(
                X + (size_t)(k0 + kr) * C + colBase + cq * 4);
            Bs[kr][cq * 4 + 0] = to_tf32(v.x);
            Bs[kr][cq * 4 + 1] = to_tf32(v.y);
            Bs[kr][cq * 4 + 2] = to_tf32(v.z);
            Bs[kr][cq * 4 + 3] = to_tf32(v.w);
        }
        __syncthreads();

#pragma unroll
        for (int ks = 0; ks < BK / 8; ++ks) {
            const int kb = ks * 8 + qid;
            uint32_t afr[MI][4];
            uint32_t bfr[NI][2];
#pragma unroll
            for (int mi = 0; mi < MI; ++mi) {
                int row = wm * WM + mi * 16 + grp;
                afr[mi][0] = __float_as_uint(As[kb    ][row    ]);
                afr[mi][1] = __float_as_uint(As[kb    ][row + 8]);
                afr[mi][2] = __float_as_uint(As[kb + 4][row    ]);
                afr[mi][3] = __float_as_uint(As[kb + 4][row + 8]);
            }
#pragma unroll
            for (int ni = 0; ni < NI; ++ni) {
                int col = wn * WN + ni * 8 + grp;
                bfr[ni][0] = __float_as_uint(Bs[kb    ][col]);
                bfr[ni][1] = __float_as_uint(Bs[kb + 4][col]);
            }
#pragma unroll
            for (int mi = 0; mi < MI; ++mi)
#pragma unroll
                for (int ni = 0; ni < NI; ++ni)
                    mma_m16n8k8(acc[mi][ni],
                                afr[mi][0], afr[mi][1], afr[mi][2], afr[mi][3],
                                bfr[ni][0], bfr[ni][1]);
        }
        __syncthreads();
    }

    // epilogue
#pragma unroll
    for (int mi = 0; mi < MI; ++mi) {
#pragma unroll
        for (int ni = 0; ni < NI; ++ni) {
            int row0 = rowBase + wm * WM + mi * 16 + grp;
            int col0 = colBase + wn * WN + ni * 8 + 2 * qid;
            float2 v01 = make_float2(acc[mi][ni][0], acc[mi][ni][1]);
            float2 v23 = make_float2(acc[mi][ni][2], acc[mi][ni][3]);
            *reinterpret_cast<float2*>(Y + (size_t)row0 * C + col0)       = v01;
            *reinterpret_cast<float2*>(Y + (size_t)(row0 + 8) * C + col0) = v23;
        }
    }
}

// K3: p0 = adj@xcat, p1 = adjT@xcat  (C=128). z: b = z&15, sel = z>>4.
__global__ __launch_bounds__(256, 2)
void k3_mma128()
{
    __shared__ float As[32][136];
    __shared__ float Bs[32][136];
    int z   = blockIdx.z;
    int b   = z & 15;
    int sel = z >> 4;
    const float* A = g_adj + (size_t)b * NSQ;
    float*       Y = (sel ? g_p1 : g_p0) + (size_t)b * N_ * 128;
    mma_core<128, 128, 32, 2, 4>(A, g_xcat + (size_t)b * N_ * 128, Y,
                                 N_, 128, N_, sel != 0, As, Bs);
}

// K6: q0 = adj@rh, q1 = adjT@rh  (C=64)
__global__ __launch_bounds__(256, 2)
void k6_mma64()
{
    __shared__ float As[32][136];
    __shared__ float Bs[32][72];
    int z   = blockIdx.z;
    int b   = z & 15;
    int sel = z >> 4;
    const float* A = g_adj + (size_t)b * NSQ;
    float*       Y = (sel ? g_q1 : g_q0) + (size_t)b * N_ * 64;
    mma_core<128, 64, 32, 4, 2>(A, g_rh + (size_t)b * N_ * 64, Y,
                                N_, 64, N_, sel != 0, As, Bs);
}

// K4b: gate projection  val = xeff @ w1t   (M=16384, Kd=384, C=128)
__global__ __launch_bounds__(256, 2)
void k4b_mma_gate()
{
    __shared__ float As[32][136];
    __shared__ float Bs[32][136];
    mma_core<128, 128, 32, 2, 4>(g_xeff, g_w1t, g_val, 384, 128, 384, false, As, Bs);
}

// K8: candidate projection  cpre = xeff @ w2t  (M=16384, Kd=384, C=64)
__global__ __launch_bounds__(256, 2)
void k8_mma_cand()
{
    __shared__ float As[32][136];
    __shared__ float Bs[32][72];
    mma_core<128, 64, 32, 4, 2>(g_xeff, g_w2t, g_cpre, 384, 64, 384, false, As, Bs);
}

// ---------------------------------------------------------------------------
// K4: effective gate input:
// xeff = [ xcat | (p0+xcat)/(colsum+1) | (p1+xcat)/(rowsum+1) ]
// ---------------------------------------------------------------------------
__global__ void k4_xeff1()
{
    size_t idx = (size_t)blockIdx.x * blockDim.x + threadIdx.x;
    if (idx >= (size_t)NB * 384) return;
    size_t node = idx / 384;
    int k = (int)(idx % 384);
    float v;
    if (k < 128) {
        v = g_xcat[node * 128 + k];
    } else if (k < 256) {
        int c = k - 128;
        v = (g_p0[node * 128 + c] + g_xcat[node * 128 + c]) / (g_colsum[node] + 1.f);
    } else {
        int c = k - 256;
        v = (g_p1[node * 128 + c] + g_xcat[node * 128 + c]) / (g_rowsum[node] + 1.f);
    }
    g_xeff[idx] = v;
}

// ---------------------------------------------------------------------------
// K5: gates r,u = sigmoid(val + bias); rh = r*h; keep u
// ---------------------------------------------------------------------------
__global__ void k5_act(const float* __restrict__ hx)
{
    size_t idx = (size_t)blockIdx.x * blockDim.x + threadIdx.x;
    if (idx >= (size_t)NB * 64) return;
    size_t node = idx / 64;
    int o = (int)(idx % 64);
    float r = 1.f / (1.f + __expf(-(g_val[node * 128 + o]      + g_b1[o])));
    float u = 1.f / (1.f + __expf(-(g_val[node * 128 + 64 + o] + g_b1[64 + o])));
    g_u[idx]  = u;
    g_rh[idx] = r * hx[idx];
}

// ---------------------------------------------------------------------------
// K7: effective candidate input (reuses pass-1 p0/p1 for xin channels;
// only r*h channels needed the new SpMM q0/q1)
// ---------------------------------------------------------------------------
__global__ void k7_xeff2()
{
    size_t idx = (size_t)blockIdx.x * blockDim.x + threadIdx.x;
    if (idx >= (size_t)NB * 384) return;
    size_t node = idx / 384;
    int k = (int)(idx % 384);
    float invc = 1.f / (g_colsum[node] + 1.f);
    float invr = 1.f / (g_rowsum[node] + 1.f);
    float v;
    if      (k < 64)  v = g_xcat[node * 128 + k];                                         // xin
    else if (k < 128) v = g_rh[node * 64 + (k - 64)];                                     // r*h
    else if (k < 192) { int c = k - 128; v = (g_p0[node*128 + c] + g_xcat[node*128 + c]) * invc; }
    else if (k < 256) { int c = k - 192; v = (g_q0[node*64  + c] + g_rh [node*64  + c]) * invc; }
    else if (k < 320) { int c = k - 256; v = (g_p1[node*128 + c] + g_xcat[node*128 + c]) * invr; }
    else              { int c = k - 320; v = (g_q1[node*64  + c] + g_rh [node*64  + c]) * invr; }
    g_xeff[idx] = v;
}

// ---------------------------------------------------------------------------
// K9: c = tanh(cpre + bias); out = u*h + (1-u)*c
// ---------------------------------------------------------------------------
__global__ void k9_final(const float* __restrict__ hx, float* __restrict__ out)
{
    size_t idx = (size_t)blockIdx.x * blockDim.x + threadIdx.x;
    if (idx >= (size_t)NB * 64) return;
    int o = (int)(idx % 64);
    float c = tanhf(g_cpre[idx] + g_b2[o]);
    float u = g_u[idx];
    out[idx] = u * hx[idx] + (1.f - u) * c;
}

// ---------------------------------------------------------------------------
// Launch: kernel launches only (graph-capture safe)
// ---------------------------------------------------------------------------
extern "C" void kernel_launch(void* const* d_in, const int* in_sizes, int n_in,
                              void* d_out, int out_size)
{
    const float* logits = (const float*)d_in[0];
    const float* unoise = (const float*)d_in[1];
    const float* inputs = (const float*)d_in[2];
    const float* hx     = (const float*)d_in[3];
    const float* W0     = (const float*)d_in[4];
    const float* b0     = (const float*)d_in[5];
    const float* W1     = (const float*)d_in[6];
    const float* b1     = (const float*)d_in[7];
    const float* Wc0    = (const float*)d_in[8];
    const float* bc0    = (const float*)d_in[9];
    const float* Wc1    = (const float*)d_in[10];
    const float* bc1    = (const float*)d_in[11];
    float* out          = (float*)d_out;

    k0_prep<<<128, 256>>>(W0, b0, W1, b1, Wc0, bc0, Wc1, bc1);

    k1_gumbel<<<dim3(N_/32, N_/32, B_), dim3(32, 8)>>>(logits, unoise);

    k2_xcat<<<(NB * 128 + 255) / 256, 256>>>(inputs, hx);

    k3_mma128<<<dim3(1, N_/128, 2 * B_), 256>>>();

    k4_xeff1<<<(NB * 384 + 255) / 256, 256>>>();

    k4b_mma_gate<<<dim3(1, NB/128, 1), 256>>>();

    k5_act<<<(NB * 64 + 255) / 256, 256>>>(hx);

    k6_mma64<<<dim3(1, N_/128, 2 * B_), 256>>>();

    k7_xeff2<<<(NB * 384 + 255) / 256, 256>>>();

    k8_mma_cand<<<dim3(1, NB/128, 1), 256>>>();

    k9_final<<<(NB * 64 + 255) / 256, 256>>>(hx, out);
}

// round 6
// speedup vs baseline: 3.0538x; 1.8004x over previous
#include <cuda_runtime.h>
#include <cstdint>

// Problem constants
static constexpr int   B_   = 16;
static constexpr int   N_   = 1024;
static constexpr float TAU_ = 0.5f;
static constexpr float EPS_ = 1e-10f;
static constexpr int   NSQ  = N_ * N_;        // 1048576
static constexpr int   NB   = B_ * N_;        // 16384 nodes total

// ---------------------------------------------------------------------------
// Scratch (device globals; allocation is forbidden)
// xeff layout per node (384 floats):
//   [  0.. 63] xin
//   [ 64..127] h        (pass 1)  ->  r*h   (overwritten by k4b epilogue)
//   [128..191] P0x = ((adj @x)+x)_xin * invc
//   [192..255] P0h (pass 1)       ->  Q0 = ((adj @rh)+rh)*invc (k6 epilogue)
//   [256..319] P1x = ((adjT@x)+x)_xin * invr
//   [320..383] P1h (pass 1)       ->  Q1 = ((adjT@rh)+rh)*invr (k6 epilogue)
// ---------------------------------------------------------------------------
__device__ float g_adj  [B_ * NSQ];          // 64 MB  adj[b,i,j]
__device__ float g_rowsum[NB];               // sum_j adj[i,j]
__device__ float g_colsum[NB];               // sum_i adj[i,j]
__device__ float g_xeff [NB * 384];
__device__ float g_u    [NB * 64];           // update gate
__device__ float g_w1t  [384 * 128];         // gate weights, (k,o'), o' interleaved r/u
__device__ float g_w2t  [384 * 64];          // candidate weights, (k,o)
__device__ float g_b1   [128];               // interleaved r/u bias
__device__ float g_b2   [64];

// ---------------------------------------------------------------------------
// cp.async helpers
// ---------------------------------------------------------------------------
__device__ __forceinline__ void cp_async16(void* smem_dst, const void* gsrc)
{
    uint32_t s = (uint32_t)__cvta_generic_to_shared(smem_dst);
    asm volatile("cp.async.cg.shared.global [%0], [%1], 16;\n" :: "r"(s), "l"(gsrc));
}
__device__ __forceinline__ void cp_commit() { asm volatile("cp.async.commit_group;\n"); }
__device__ __forceinline__ void cp_wait1()  { asm volatile("cp.async.wait_group 1;\n"); }
__device__ __forceinline__ void cp_wait0()  { asm volatile("cp.async.wait_group 0;\n"); }

__device__ __forceinline__ void mma_m16n8k8(float c[4],
                                            uint32_t a0, uint32_t a1, uint32_t a2, uint32_t a3,
                                            uint32_t b0, uint32_t b1)
{
    asm volatile("mma.sync.aligned.m16n8k8.row.col.f32.tf32.tf32.f32 "
                 "{%0,%1,%2,%3}, {%4,%5,%6,%7}, {%8,%9}, {%0,%1,%2,%3};\n"
                 : "+f"(c[0]), "+f"(c[1]), "+f"(c[2]), "+f"(c[3])
                 : "r"(a0), "r"(a1), "r"(a2), "r"(a3), "r"(b0), "r"(b1));
}

// ---------------------------------------------------------------------------
// Pipelined TF32 MMA core (double-buffered cp.async, BK=16).
//   AKM=false: A row-major (element (m,k) at A[m*ldA+k]); smem A [BM][20]
//   AKM=true : A K-major   (element (m,k) at A[k*ldA+m]); smem A [16][BM+8]
// Raw fp32 bits are fed to the TF32 MMA (hardware truncates to 19 bits).
// Canonical pipeline: never commits an empty cp.async group.
// Epi(rowGlobal, colLocal, v0, v1, v2, v3): values at (row,col),(row,col+1),
// (row+8,col),(row+8,col+1); col is always even.
// ---------------------------------------------------------------------------
template<int BM, int BN, int WARPS_M, int WARPS_N, bool AKM, class Epi>
__device__ __forceinline__ void mma_pipe(const float* __restrict__ A,
                                         const float* __restrict__ X,
                                         int Kd, int ldA, int ldX,
                                         int rowBase, char* sbuf, Epi epi)
{
    constexpr int BK      = 16;
    constexpr int THREADS = WARPS_M * WARPS_N * 32;
    constexpr int WM = BM / WARPS_M;
    constexpr int WN = BN / WARPS_N;
    constexpr int MI = WM / 16;
    constexpr int NI = WN / 8;
    constexpr int A_ST_RM = BK + 4;        // 20 floats
    constexpr int A_ST_KM = BM + 8;        // 136 floats
    constexpr int A_FLOATS = AKM ? BK * A_ST_KM : BM * A_ST_RM;
    constexpr int B_ST = BN + 8;
    constexpr int B_FLOATS = BK * B_ST;

    float* As0 = (float*)sbuf;
    float* As1 = As0 + A_FLOATS;
    float* Bs0 = As1 + A_FLOATS;
    float* Bs1 = Bs0 + B_FLOATS;

    const int tid  = threadIdx.x;
    const int lane = tid & 31;
    const int w    = tid >> 5;
    const int wm   = w / WARPS_N;
    const int wn   = w % WARPS_N;
    const int grp  = lane >> 2;     // 0..7
    const int qid  = lane & 3;      // 0..3

    float acc[MI][NI][4];
#pragma unroll
    for (int mi = 0; mi < MI; ++mi)
#pragma unroll
        for (int ni = 0; ni < NI; ++ni)
#pragma unroll
            for (int r = 0; r < 4; ++r) acc[mi][ni][r] = 0.f;

    auto load_stage = [&](int s, int k0) {
        float* As = s ? As1 : As0;
        float* Bs = s ? Bs1 : Bs0;
        if (AKM) {
#pragma unroll
            for (int i = tid; i < BK * (BM / 4); i += THREADS) {
                int kr = i / (BM / 4), mq = i % (BM / 4);
                cp_async16(As + kr * A_ST_KM + mq * 4,
                           A + (size_t)(k0 + kr) * ldA + rowBase + mq * 4);
            }
        } else {
#pragma unroll
            for (int i = tid; i < BM * (BK / 4); i += THREADS) {
                int m = i / (BK / 4), kq = i % (BK / 4);
                cp_async16(As + m * A_ST_RM + kq * 4,
                           A + (size_t)(rowBase + m) * ldA + k0 + kq * 4);
            }
        }
#pragma unroll
        for (int i = tid; i < BK * (BN / 4); i += THREADS) {
            int kr = i / (BN / 4), cq = i % (BN / 4);
            cp_async16(Bs + kr * B_ST + cq * 4,
                       X + (size_t)(k0 + kr) * ldX + cq * 4);
        }
    };

    load_stage(0, 0);
    cp_commit();

    const int nIter = Kd / BK;
    for (int it = 0; it < nIter; ++it) {
        const int cur = it & 1;
        if (it + 1 < nIter) {
            load_stage(cur ^ 1, (it + 1) * BK);
            cp_commit();
            cp_wait1();            // retire the group for `cur`; next stays in flight
        } else {
            cp_wait0();            // last tile: drain everything
        }
        __syncthreads();

        const float* As = cur ? As1 : As0;
        const float* Bs = cur ? Bs1 : Bs0;

#pragma unroll
        for (int ks = 0; ks < BK / 8; ++ks) {
            const int kb = ks * 8 + qid;
            uint32_t afr[MI][4];
            uint32_t bfr[NI][2];
#pragma unroll
            for (int mi = 0; mi < MI; ++mi) {
                int row = wm * WM + mi * 16 + grp;
                if (AKM) {
                    afr[mi][0] = __float_as_uint(As[(kb    ) * A_ST_KM + row    ]);
                    afr[mi][1] = __float_as_uint(As[(kb    ) * A_ST_KM + row + 8]);
                    afr[mi][2] = __float_as_uint(As[(kb + 4) * A_ST_KM + row    ]);
                    afr[mi][3] = __float_as_uint(As[(kb + 4) * A_ST_KM + row + 8]);
                } else {
                    afr[mi][0] = __float_as_uint(As[(row    ) * A_ST_RM + kb    ]);
                    afr[mi][1] = __float_as_uint(As[(row + 8) * A_ST_RM + kb    ]);
                    afr[mi][2] = __float_as_uint(As[(row    ) * A_ST_RM + kb + 4]);
                    afr[mi][3] = __float_as_uint(As[(row + 8) * A_ST_RM + kb + 4]);
                }
            }
#pragma unroll
            for (int ni = 0; ni < NI; ++ni) {
                int col = wn * WN + ni * 8 + grp;
                bfr[ni][0] = __float_as_uint(Bs[(kb    ) * B_ST + col]);
                bfr[ni][1] = __float_as_uint(Bs[(kb + 4) * B_ST + col]);
            }
#pragma unroll
            for (int mi = 0; mi < MI; ++mi)
#pragma unroll
                for (int ni = 0; ni < NI; ++ni)
                    mma_m16n8k8(acc[mi][ni],
                                afr[mi][0], afr[mi][1], afr[mi][2], afr[mi][3],
                                bfr[ni][0], bfr[ni][1]);
        }
        __syncthreads();
    }

#pragma unroll
    for (int mi = 0; mi < MI; ++mi)
#pragma unroll
        for (int ni = 0; ni < NI; ++ni) {
            int row = rowBase + wm * WM + mi * 16 + grp;
            int col = wn * WN + ni * 8 + 2 * qid;
            epi(row, col, acc[mi][ni][0], acc[mi][ni][1], acc[mi][ni][2], acc[mi][ni][3]);
        }
}

// ---------------------------------------------------------------------------
// K0: fold weights. Reference's diffusion appends `prev` twice (A^2 x unused)
// so steps 1+2 share Ax -> pre-sum those weight columns. w1t output columns
// interleaved: o'=2o -> r-channel o, o'=2o+1 -> u-channel o (orig row o+64).
// ---------------------------------------------------------------------------
__global__ void k0_prep(const float* __restrict__ W0, const float* __restrict__ b0,
                        const float* __restrict__ W1, const float* __restrict__ b1,
                        const float* __restrict__ Wc0, const float* __restrict__ bc0,
                        const float* __restrict__ Wc1, const float* __restrict__ bc1)
{
    int idx    = blockIdx.x * blockDim.x + threadIdx.x;
    int stride = gridDim.x * blockDim.x;

    for (int i = idx; i < 384 * 128; i += stride) {
        int k = i / 128, o = i % 128;
        int orig = (o & 1) ? (o >> 1) + 64 : (o >> 1);     // interleave r/u
        float v;
        if (k < 128)       { int c = k;        v = W0[orig*384 + 3*c]     + W1[orig*384 + 3*c];     }
        else if (k < 256)  { int c = k - 128;  v = W0[orig*384 + 3*c + 1] + W0[orig*384 + 3*c + 2]; }
        else               { int c = k - 256;  v = W1[orig*384 + 3*c + 1] + W1[orig*384 + 3*c + 2]; }
        g_w1t[i] = v;
    }
    for (int i = idx; i < 384 * 64; i += stride) {
        int k = i / 64, o = i % 64;
        float v;
        if (k < 128)       { int c = k;        v = Wc0[o*384 + 3*c]     + Wc1[o*384 + 3*c];     }
        else if (k < 256)  { int c = k - 128;  v = Wc0[o*384 + 3*c + 1] + Wc0[o*384 + 3*c + 2]; }
        else               { int c = k - 256;  v = Wc1[o*384 + 3*c + 1] + Wc1[o*384 + 3*c + 2]; }
        g_w2t[i] = v;
    }
    for (int i = idx; i < 128; i += stride) {
        int orig = (i & 1) ? (i >> 1) + 64 : (i >> 1);
        g_b1[i] = b0[orig] + b1[orig];
    }
    for (int i = idx; i < 64;  i += stride) g_b2[i] = bc0[i] + bc1[i];
    for (int i = idx; i < NB;  i += stride) { g_rowsum[i] = 0.f; g_colsum[i] = 0.f; }
}

// ---------------------------------------------------------------------------
// K1: Gumbel-softmax adjacency + row/col sums (fused).
// z_i = l_i - log(g_i), g_i = EPS - log(u_i + EPS)
// adj = softmax(z/tau)[0] = 1 / (1 + exp((z1 - z0)/tau))
// ---------------------------------------------------------------------------
__global__ void k1_gumbel(const float* __restrict__ logits,
                          const float* __restrict__ unoise)
{
    __shared__ float scol[8][32];

    const int b  = blockIdx.z;
    const int i0 = blockIdx.y * 32;
    const int j0 = blockIdx.x * 32;
    const int tx = threadIdx.x;
    const int ty = threadIdx.y;

    const float2* lg = reinterpret_cast<const float2*>(logits) + (size_t)b * NSQ;
    const float2* un = reinterpret_cast<const float2*>(unoise) + (size_t)b * NSQ;

    float vals[4];
#pragma unroll
    for (int sI = 0; sI < 4; ++sI) {
        int row  = ty + 8 * sI;
        size_t e = (size_t)(i0 + row) * N_ + (j0 + tx);
        float2 l = lg[e];
        float2 u = un[e];
        float g0 = EPS_ - __logf(u.x + EPS_);
        float g1 = EPS_ - __logf(u.y + EPS_);
        float t  = ((l.y - l.x) + (__logf(g0) - __logf(g1))) * (1.0f / TAU_);
        float a  = 1.0f / (1.0f + __expf(t));
        vals[sI] = a;
        g_adj[(size_t)b * NSQ + e] = a;
    }

#pragma unroll
    for (int sI = 0; sI < 4; ++sI) {
        float v = vals[sI];
#pragma unroll
        for (int o = 16; o > 0; o >>= 1) v += __shfl_down_sync(0xffffffffu, v, o);
        if (tx == 0) atomicAdd(&g_rowsum[b * N_ + i0 + ty + 8 * sI], v);
    }

    scol[ty][tx] = vals[0] + vals[1] + vals[2] + vals[3];
    __syncthreads();
    if (ty == 0) {
        float t2 = 0.f;
#pragma unroll
        for (int w = 0; w < 8; ++w) t2 += scol[w][tx];
        atomicAdd(&g_colsum[b * N_ + j0 + tx], t2);
    }
}

// ---------------------------------------------------------------------------
// K2: write xin -> xeff[0..63], h -> xeff[64..127]
// ---------------------------------------------------------------------------
__global__ void k2_xcat(const float* __restrict__ inp, const float* __restrict__ hx)
{
    size_t idx = (size_t)blockIdx.x * blockDim.x + threadIdx.x;
    if (idx >= (size_t)NB * 128) return;
    size_t node = idx >> 7;
    int c = (int)(idx & 127);
    float v = (c < 64) ? inp[node * 64 + c] : hx[node * 64 + (c - 64)];
    g_xeff[node * 384 + c] = v;
}

// ---------------------------------------------------------------------------
// K3: pass-1 SpMM pair. sel0: p0 = adj@xcat, scaled by 1/(colsum+1), into
// xeff cols 128..255. sel1: p1 = adjT@xcat, 1/(rowsum+1), cols 256..383.
// Epilogue adds the identity term (x) before scaling.
// ---------------------------------------------------------------------------
static constexpr int SB_BN128 = (128*20*2 + 16*136*2) * 4;   // 37888 B
static constexpr int SB_BN64  = (128*20*2 + 16*72*2)  * 4;   // 29696 B

__global__ __launch_bounds__(256, 2)
void k3_spmm()
{
    __shared__ __align__(16) char sbuf[SB_BN128];
    int z   = blockIdx.z;
    int b   = z & 15;
    int sel = z >> 4;
    const float* A    = g_adj  + (size_t)b * NSQ;
    float*       xeff = g_xeff + (size_t)b * N_ * 384;
    const float* sums = (sel ? g_rowsum : g_colsum) + b * N_;
    const int outOff  = 128 + sel * 128;
    const int rowBase = blockIdx.y * 128;

    auto epi = [&](int row, int col, float v0, float v1, float v2, float v3) {
        float inv0 = 1.f / (sums[row]     + 1.f);
        float inv1 = 1.f / (sums[row + 8] + 1.f);
        float2 x0 = *reinterpret_cast<const float2*>(xeff + (size_t)row       * 384 + col);
        float2 x1 = *reinterpret_cast<const float2*>(xeff + (size_t)(row + 8) * 384 + col);
        float2 o0 = make_float2((v0 + x0.x) * inv0, (v1 + x0.y) * inv0);
        float2 o1 = make_float2((v2 + x1.x) * inv1, (v3 + x1.y) * inv1);
        *reinterpret_cast<float2*>(xeff + (size_t)row       * 384 + outOff + col) = o0;
        *reinterpret_cast<float2*>(xeff + (size_t)(row + 8) * 384 + outOff + col) = o1;
    };

    if (sel == 0)
        mma_pipe<128, 128, 2, 4, false>(A, xeff, N_, N_, 384, rowBase, sbuf, epi);
    else
        mma_pipe<128, 128, 2, 4, true >(A, xeff, N_, N_, 384, rowBase, sbuf, epi);
}

// ---------------------------------------------------------------------------
// K4b: gate projection + fused activation epilogue.
// val = xeff @ w1t (interleaved r/u cols). col even -> r, col odd -> u.
// writes u -> g_u, r*h -> xeff cols 64..127 (own rows only).
// ---------------------------------------------------------------------------
__global__ __launch_bounds__(256, 2)
void k4b_gate(const float* __restrict__ hx)
{
    __shared__ __align__(16) char sbuf[SB_BN128];
    const int rowBase = blockIdx.y * 128;

    auto epi = [&](int row, int col, float v0, float v1, float v2, float v3) {
        int o = col >> 1;
        float b_r = g_b1[col], b_u = g_b1[col + 1];
        float r0 = 1.f / (1.f + __expf(-(v0 + b_r)));
        float u0 = 1.f / (1.f + __expf(-(v1 + b_u)));
        float r1 = 1.f / (1.f + __expf(-(v2 + b_r)));
        float u1 = 1.f / (1.f + __expf(-(v3 + b_u)));
        g_u[(size_t)row * 64 + o]            = u0;
        g_u[(size_t)(row + 8) * 64 + o]      = u1;
        g_xeff[(size_t)row * 384 + 64 + o]       = r0 * hx[(size_t)row * 64 + o];
        g_xeff[(size_t)(row + 8) * 384 + 64 + o] = r1 * hx[(size_t)(row + 8) * 64 + o];
    };

    mma_pipe<128, 128, 2, 4, false>(g_xeff, g_w1t, 384, 384, 128, rowBase, sbuf, epi);
}

// ---------------------------------------------------------------------------
// K6: pass-2 SpMM pair over rh (xeff cols 64..127).
// sel0 -> Q0 into cols 192..255 (colsum), sel1 -> Q1 into cols 320..383 (rowsum).
// ---------------------------------------------------------------------------
__global__ __launch_bounds__(256, 2)
void k6_spmm()
{
    __shared__ __align__(16) char sbuf[SB_BN64];
    int z   = blockIdx.z;
    int b   = z & 15;
    int sel = z >> 4;
    const float* A    = g_adj  + (size_t)b * NSQ;
    float*       xeff = g_xeff + (size_t)b * N_ * 384;
    const float* sums = (sel ? g_rowsum : g_colsum) + b * N_;
    const int outOff  = 192 + sel * 128;
    const int rowBase = blockIdx.y * 128;

    auto epi = [&](int row, int col, float v0, float v1, float v2, float v3) {
        float inv0 = 1.f / (sums[row]     + 1.f);
        float inv1 = 1.f / (sums[row + 8] + 1.f);
        float2 x0 = *reinterpret_cast<const float2*>(xeff + (size_t)row       * 384 + 64 + col);
        float2 x1 = *reinterpret_cast<const float2*>(xeff + (size_t)(row + 8) * 384 + 64 + col);
        float2 o0 = make_float2((v0 + x0.x) * inv0, (v1 + x0.y) * inv0);
        float2 o1 = make_float2((v2 + x1.x) * inv1, (v3 + x1.y) * inv1);
        *reinterpret_cast<float2*>(xeff + (size_t)row       * 384 + outOff + col) = o0;
        *reinterpret_cast<float2*>(xeff + (size_t)(row + 8) * 384 + outOff + col) = o1;
    };

    if (sel == 0)
        mma_pipe<128, 64, 4, 2, false>(A, xeff + 64, N_, N_, 384, rowBase, sbuf, epi);
    else
        mma_pipe<128, 64, 4, 2, true >(A, xeff + 64, N_, N_, 384, rowBase, sbuf, epi);
}

// ---------------------------------------------------------------------------
// K8: candidate projection + fused final GRU epilogue.
// c = tanh(xeff @ w2t + b2); out = u*h + (1-u)*c
// ---------------------------------------------------------------------------
__global__ __launch_bounds__(256, 2)
void k8_cand(const float* __restrict__ hx, float* __restrict__ out)
{
    __shared__ __align__(16) char sbuf[SB_BN64];
    const int rowBase = blockIdx.y * 128;

    auto epi = [&](int row, int col, float v0, float v1, float v2, float v3) {
        float b0v = g_b2[col], b1v = g_b2[col + 1];
        float c00 = tanhf(v0 + b0v), c01 = tanhf(v1 + b1v);
        float c10 = tanhf(v2 + b0v), c11 = tanhf(v3 + b1v);
        size_t i0 = (size_t)row * 64 + col;
        size_t i1 = (size_t)(row + 8) * 64 + col;
        float2 u0 = *reinterpret_cast<const float2*>(g_u + i0);
        float2 u1 = *reinterpret_cast<const float2*>(g_u + i1);
        float2 h0 = *reinterpret_cast<const float2*>(hx + i0);
        float2 h1 = *reinterpret_cast<const float2*>(hx + i1);
        float2 o0 = make_float2(u0.x * h0.x + (1.f - u0.x) * c00,
                                u0.y * h0.y + (1.f - u0.y) * c01);
        float2 o1 = make_float2(u1.x * h1.x + (1.f - u1.x) * c10,
                                u1.y * h1.y + (1.f - u1.y) * c11);
        *reinterpret_cast<float2*>(out + i0) = o0;
        *reinterpret_cast<float2*>(out + i1) = o1;
    };

    mma_pipe<128, 64, 4, 2, false>(g_xeff, g_w2t, 384, 384, 64, rowBase, sbuf, epi);
}

// ---------------------------------------------------------------------------
// Launch: kernel launches only (graph-capture safe)
// ---------------------------------------------------------------------------
extern "C" void kernel_launch(void* const* d_in, const int* in_sizes, int n_in,
                              void* d_out, int out_size)
{
    const float* logits = (const float*)d_in[0];
    const float* unoise = (const float*)d_in[1];
    const float* inputs = (const float*)d_in[2];
    const float* hx     = (const float*)d_in[3];
    const float* W0     = (const float*)d_in[4];
    const float* b0     = (const float*)d_in[5];
    const float* W1     = (const float*)d_in[6];
    const float* b1     = (const float*)d_in[7];
    const float* Wc0    = (const float*)d_in[8];
    const float* bc0    = (const float*)d_in[9];
    const float* Wc1    = (const float*)d_in[10];
    const float* bc1    = (const float*)d_in[11];
    float* out          = (float*)d_out;

    k0_prep<<<128, 256>>>(W0, b0, W1, b1, Wc0, bc0, Wc1, bc1);

    k1_gumbel<<<dim3(N_/32, N_/32, B_), dim3(32, 8)>>>(logits, unoise);

    k2_xcat<<<(NB * 128 + 255) / 256, 256>>>(inputs, hx);

    k3_spmm<<<dim3(1, N_/128, 2 * B_), 256>>>();

    k4b_gate<<<dim3(1, NB/128, 1), 256>>>(hx);

    k6_spmm<<<dim3(1, N_/128, 2 * B_), 256>>>();

    k8_cand<<<dim3(1, NB/128, 1), 256>>>(hx, out);
}